// round 15
// baseline (speedup 1.0000x reference)
#include <cuda_runtime.h>
#include <cuda_bf16.h>
#include <cstdint>
#include <math.h>

#define BB 8
#define SS 2048
#define HH 1024
#define DD 64
#define BS (BB*SS)      /* 16384 */
#define QKV_LD 192

#define CLIP_HI 0.9999998807907104f
#define PEXP (-65.5f)

// ---------------------------------------------------------------- scratch
__device__ float g_qkv[BS * QKV_LD];               // [row][ q(64) | k(64) | v(64) ]
__device__ float g_colsum[BS];                     // [B][S]
__device__ float g_rdi[BS];                        // [B][S] 1/rowdot
__device__ __nv_bfloat16 g_qsp[(size_t)BS * 128];  // [row][ q_hi(64) | q_lo(64) ]
__device__ __nv_bfloat16 g_ksp[(size_t)BS * 128];  // [row][ k_hi(64) | k_lo(64) ]

// ---------------------------------------------------------------- warp MMA helpers (arch-stable PTX)
__device__ __forceinline__ uint32_t smem_to_u32(const void* smem_ptr) {
    uint32_t addr;
    asm("{ .reg .u64 tmp; cvta.to.shared.u64 tmp, %1; cvt.u32.u64 %0, tmp; }"
        : "=r"(addr) : "l"(smem_ptr));
    return addr;
}

__device__ __forceinline__ void ldsm_x4(uint32_t* r, uint32_t addr) {
    asm volatile("ldmatrix.sync.aligned.m8n8.x4.shared.b16 {%0,%1,%2,%3}, [%4];"
        : "=r"(r[0]), "=r"(r[1]), "=r"(r[2]), "=r"(r[3]) : "r"(addr));
}
__device__ __forceinline__ void ldsm_x4_t(uint32_t* r, uint32_t addr) {
    asm volatile("ldmatrix.sync.aligned.m8n8.x4.trans.shared.b16 {%0,%1,%2,%3}, [%4];"
        : "=r"(r[0]), "=r"(r[1]), "=r"(r[2]), "=r"(r[3]) : "r"(addr));
}
__device__ __forceinline__ void mma_bf16(float* d, const uint32_t* a, const uint32_t* b) {
    asm volatile(
        "mma.sync.aligned.m16n8k16.row.col.f32.bf16.bf16.f32 "
        "{%0,%1,%2,%3}, {%4,%5,%6,%7}, {%8,%9}, {%0,%1,%2,%3};"
        : "+f"(d[0]), "+f"(d[1]), "+f"(d[2]), "+f"(d[3])
        : "r"(a[0]), "r"(a[1]), "r"(a[2]), "r"(a[3]), "r"(b[0]), "r"(b[1]));
}

__device__ __forceinline__ float score_fn(float cosv) {
    cosv = fminf(fmaxf(cosv, -CLIP_HI), CLIP_HI);
    float gd = acosf(cosv);
    float l;
    asm("lg2.approx.f32 %0, %1;" : "=f"(l) : "f"(1.0f + gd));
    float e;
    asm("ex2.approx.f32 %0, %1;" : "=f"(e) : "f"(PEXP * l));
    return e;
}

__device__ __forceinline__ __nv_bfloat162 split_hi2(float a, float b,
                                                    float& ra, float& rb) {
    __nv_bfloat16 h0 = __float2bfloat16(a);
    __nv_bfloat16 h1 = __float2bfloat16(b);
    ra = a - __bfloat162float(h0);
    rb = b - __bfloat162float(h1);
    return __halves2bfloat162(h0, h1);
}

// ---------------------------------------------------------------- K1: fused q|k|v projections via bf16 3-split mma (proven R13)
#define K1_AK 72
#define K1_BK 392

__global__ __launch_bounds__(256, 2) void k1_proj(
    const float* __restrict__ x,
    const float* __restrict__ Wq, const float* __restrict__ bq,
    const float* __restrict__ Wk, const float* __restrict__ bk,
    const float* __restrict__ Wv, const float* __restrict__ bv)
{
    __shared__ __nv_bfloat16 As[64][K1_AK];
    __shared__ __nv_bfloat16 Bs[32][K1_BK];
    __shared__ float s_bias[192];

    const int m0 = blockIdx.x * 64;
    const int tid = threadIdx.x;
    const int wid = tid >> 5, lane = tid & 31;
    const int wm = wid & 3, wn = wid >> 2;

    if (tid < 192) {
        const float* bsrc = (tid < 64) ? bq : ((tid < 128) ? bk : bv);
        s_bias[tid] = bsrc[tid & 63];
    }

    float acc[12][4];
#pragma unroll
    for (int nb = 0; nb < 12; nb++)
#pragma unroll
        for (int i = 0; i < 4; i++) acc[nb][i] = 0.0f;

    const uint32_t Ab = smem_to_u32(As), Bb = smem_to_u32(Bs);
    const uint32_t aBase = Ab + (uint32_t)((wm * 16 + (lane & 15)) * K1_AK + (lane >> 4) * 8) * 2;
    const int bkrow = (lane & 7) + 8 * ((lane >> 3) & 1);
    const uint32_t bBase = Bb + (uint32_t)(bkrow * K1_BK + wn * 96 + 8 * (lane >> 4)) * 2;

    for (int k0 = 0; k0 < HH; k0 += 32) {
#pragma unroll
        for (int it = 0; it < 2; it++) {
            int f = tid + 256 * it;
            int row = f >> 3;
            int k4 = (f & 7) * 4;
            float4 v = *(const float4*)(x + (size_t)(m0 + row) * HH + k0 + k4);
            float r0, r1, r2, r3;
            __nv_bfloat162 h01 = split_hi2(v.x, v.y, r0, r1);
            __nv_bfloat162 h23 = split_hi2(v.z, v.w, r2, r3);
            *(__nv_bfloat162*)&As[row][k4]          = h01;
            *(__nv_bfloat162*)&As[row][k4 + 2]      = h23;
            *(__nv_bfloat162*)&As[row][32 + k4]     = __halves2bfloat162(__float2bfloat16(r0), __float2bfloat16(r1));
            *(__nv_bfloat162*)&As[row][32 + k4 + 2] = __halves2bfloat162(__float2bfloat16(r2), __float2bfloat16(r3));
        }
#pragma unroll
        for (int it = 0; it < 6; it++) {
            int f = tid + 256 * it;
            int which = f >> 9;
            int kr = (f >> 4) & 31;
            int n4 = (f & 15) * 4;
            const float* W = (which == 0) ? Wq : ((which == 1) ? Wk : Wv);
            float4 v = *(const float4*)(W + (size_t)(k0 + kr) * DD + n4);
            int n = which * 64 + n4;
            float r0, r1, r2, r3;
            __nv_bfloat162 h01 = split_hi2(v.x, v.y, r0, r1);
            __nv_bfloat162 h23 = split_hi2(v.z, v.w, r2, r3);
            *(__nv_bfloat162*)&Bs[kr][n]           = h01;
            *(__nv_bfloat162*)&Bs[kr][n + 2]       = h23;
            *(__nv_bfloat162*)&Bs[kr][192 + n]     = __halves2bfloat162(__float2bfloat16(r0), __float2bfloat16(r1));
            *(__nv_bfloat162*)&Bs[kr][192 + n + 2] = __halves2bfloat162(__float2bfloat16(r2), __float2bfloat16(r3));
        }
        __syncthreads();

#pragma unroll
        for (int ks = 0; ks < 2; ks++) {
            const int kk = ks * 16;
            uint32_t ah[4], al[4];
            ldsm_x4(ah, aBase + (uint32_t)kk * 2);
            ldsm_x4(al, aBase + (uint32_t)(32 + kk) * 2);
#pragma unroll
            for (int nt = 0; nt < 6; nt++) {
                uint32_t bh[4], bl[4];
                ldsm_x4_t(bh, bBase + (uint32_t)(kk * K1_BK + nt * 16) * 2);
                ldsm_x4_t(bl, bBase + (uint32_t)(kk * K1_BK + 192 + nt * 16) * 2);
#pragma unroll
                for (int p = 0; p < 2; p++) {
                    const int nb = nt * 2 + p;
                    mma_bf16(acc[nb], ah, &bh[p * 2]);
                    mma_bf16(acc[nb], al, &bh[p * 2]);
                    mma_bf16(acc[nb], ah, &bl[p * 2]);
                }
            }
        }
        __syncthreads();
    }

    const int g8 = lane >> 2, l4 = lane & 3;
#pragma unroll
    for (int nb = 0; nb < 12; nb++) {
        int col = wn * 96 + nb * 8 + l4 * 2;
        float2 bb = *(float2*)&s_bias[col];
        int row = m0 + wm * 16 + g8;
        *(float2*)(g_qkv + (size_t)row * QKV_LD + col) =
            make_float2(acc[nb][0] + bb.x, acc[nb][1] + bb.y);
        *(float2*)(g_qkv + (size_t)(row + 8) * QKV_LD + col) =
            make_float2(acc[nb][2] + bb.x, acc[nb][3] + bb.y);
    }
}

// ---------------------------------------------------------------- K2: L2 normalize + bf16 hi/lo split + colsum zero (k0 fused)
__global__ void k2_norm() {
    int gt = blockIdx.x * blockDim.x + threadIdx.x;
    if (gt < BS) g_colsum[gt] = 0.0f;
    int gw = gt >> 5;
    int lane = threadIdx.x & 31;
    if (gw >= BS * 3) return;
    int row = gw / 3;
    int mat = gw - row * 3;
    float* p = g_qkv + (size_t)row * QKV_LD + mat * 64;
    float2 v = *(float2*)(p + lane * 2);
    float ss = v.x * v.x + v.y * v.y;
#pragma unroll
    for (int o = 16; o; o >>= 1) ss += __shfl_xor_sync(0xFFFFFFFFu, ss, o);
    float inv = 1.0f / fmaxf(sqrtf(ss), 1e-12f);
    float a0 = v.x * inv, a1 = v.y * inv;
    if (mat == 2) {
        *(float2*)(p + lane * 2) = make_float2(a0, a1);
    } else {
        __nv_bfloat16* dst = (mat == 0 ? g_qsp : g_ksp) + (size_t)row * 128;
        __nv_bfloat16 h0 = __float2bfloat16(a0);
        __nv_bfloat16 h1 = __float2bfloat16(a1);
        __nv_bfloat16 l0 = __float2bfloat16(a0 - __bfloat162float(h0));
        __nv_bfloat16 l1 = __float2bfloat16(a1 - __bfloat162float(h1));
        *(__nv_bfloat162*)(dst + lane * 2)      = __halves2bfloat162(h0, h1);
        *(__nv_bfloat162*)(dst + 64 + lane * 2) = __halves2bfloat162(l0, l1);
    }
}

// ---------------------------------------------------------------- K3: QK^T via mma.sync bf16 4-split, 128x128 tile, 512 threads
// 16 warps: (wid&3) -> 32-row band, (wid>>2) -> 32-col band (4x4 grid of 32x32).
#define LDA 136
#define K3_SMEM (2 * 128 * LDA * 2)   /* 69632 bytes */

__global__ __launch_bounds__(512, 2) void k3_score(float* __restrict__ probs)
{
    extern __shared__ __nv_bfloat16 sm[];
    __nv_bfloat16* As = sm;
    __nv_bfloat16* Bs = sm + 128 * LDA;
    __shared__ float s_colsum[128];

    const int b  = blockIdx.z;
    const int m0 = blockIdx.y * 128;
    const int n0 = blockIdx.x * 128;
    const int tid = threadIdx.x;
    const int wid = tid >> 5, lane = tid & 31;

    if (tid < 128) s_colsum[tid] = 0.0f;

    const uint4* qg = (const uint4*)(g_qsp + (size_t)(b * SS + m0) * 128);
    const uint4* kg = (const uint4*)(g_ksp + (size_t)(b * SS + n0) * 128);
#pragma unroll
    for (int it = 0; it < 4; it++) {
        int f = tid + 512 * it;              // 0..2047
        int row = f >> 4;
        int i = f & 15;
        *(uint4*)((char*)As + row * (LDA * 2) + i * 16) = qg[row * 16 + i];
        *(uint4*)((char*)Bs + row * (LDA * 2) + i * 16) = kg[row * 16 + i];
    }
    __syncthreads();

    const uint32_t Ab = smem_to_u32(As), Bb = smem_to_u32(Bs);
    const int arow = lane & 15, ak8 = (lane >> 4) * 8;
    const uint32_t aBase = Ab + (uint32_t)(((wid & 3) * 32 + arow) * LDA + ak8) * 2;
    const int bn  = (lane & 7) + ((lane >> 4) << 3);
    const int bk8 = ((lane >> 3) & 1) * 8;
    const uint32_t bBase = Bb + (uint32_t)(((wid >> 2) * 32 + bn) * LDA + bk8) * 2;

    float acc[2][4][4];
#pragma unroll
    for (int mt = 0; mt < 2; mt++)
#pragma unroll
        for (int nb = 0; nb < 4; nb++)
#pragma unroll
            for (int i = 0; i < 4; i++) acc[mt][nb][i] = 0.0f;

    const int ai[4] = {0, 1, 0, 1};
    const int bi[4] = {0, 0, 1, 1};
#pragma unroll
    for (int seg = 0; seg < 4; seg++) {
        const int aoff = ai[seg] * 64, boff = bi[seg] * 64;
#pragma unroll
        for (int ks = 0; ks < 4; ks++) {
            const int k0 = ks * 16;
            uint32_t af[2][4];
            ldsm_x4(af[0], aBase + (uint32_t)(aoff + k0) * 2);
            ldsm_x4(af[1], aBase + (uint32_t)(16 * LDA + aoff + k0) * 2);
            uint32_t bf[2][4];
#pragma unroll
            for (int nt = 0; nt < 2; nt++)
                ldsm_x4(bf[nt], bBase + (uint32_t)(nt * 16 * LDA + boff + k0) * 2);
#pragma unroll
            for (int mt = 0; mt < 2; mt++)
#pragma unroll
                for (int nb = 0; nb < 4; nb++)
                    mma_bf16(acc[mt][nb], af[mt], &bf[nb >> 1][(nb & 1) * 2]);
        }
    }

    const int g = lane >> 2, cq = (lane & 3) * 2;
    const int colbase = n0 + (wid >> 2) * 32 + cq;
    float* pb = probs + (size_t)b * SS * SS;

    float colacc[8];
#pragma unroll
    for (int i = 0; i < 8; i++) colacc[i] = 0.0f;

#pragma unroll
    for (int mt = 0; mt < 2; mt++) {
#pragma unroll
        for (int h = 0; h < 2; h++) {
            const int row = m0 + (wid & 3) * 32 + mt * 16 + h * 8 + g;
            float* rp = pb + (size_t)row * SS + colbase;
#pragma unroll
            for (int nb = 0; nb < 4; nb++) {
                float x0 = score_fn(acc[mt][nb][h * 2 + 0]);
                float x1 = score_fn(acc[mt][nb][h * 2 + 1]);
                colacc[nb * 2 + 0] += x0;
                colacc[nb * 2 + 1] += x1;
                *(float2*)(rp + nb * 8) = make_float2(x0, x1);
            }
        }
    }

#pragma unroll
    for (int nb = 0; nb < 4; nb++) {
        float s0 = colacc[nb * 2], s1 = colacc[nb * 2 + 1];
#pragma unroll
        for (int o = 4; o <= 16; o <<= 1) {
            s0 += __shfl_xor_sync(0xFFFFFFFFu, s0, o);
            s1 += __shfl_xor_sync(0xFFFFFFFFu, s1, o);
        }
        if (lane < 4) {
            atomicAdd(&s_colsum[(wid >> 2) * 32 + nb * 8 + lane * 2 + 0], s0);
            atomicAdd(&s_colsum[(wid >> 2) * 32 + nb * 8 + lane * 2 + 1], s1);
        }
    }

    __syncthreads();
    if (tid < 128) atomicAdd(&g_colsum[b * SS + n0 + tid], s_colsum[tid]);
}

// ---------------------------------------------------------------- K4a: out = (S_raw @ (c*v)) * rdi (proven R14)
#define K4_LDA 264
#define K4_LDB 136
#define K4_SMEM ((64 * K4_LDA + 128 * K4_LDB) * 2)   /* 68608 bytes */

__global__ __launch_bounds__(512, 2) void k4a_gemm(float* __restrict__ out, const float* __restrict__ probs)
{
    extern __shared__ __nv_bfloat16 k4sm[];
    __nv_bfloat16* As = k4sm;                   // [64][K4_LDA]  raw s hi|lo
    __nv_bfloat16* Bs = k4sm + 64 * K4_LDA;     // [128][K4_LDB] w=c*v hi|lo
    __shared__ float c_s[SS];
    __shared__ float rowdot_s[64];

    const int b  = blockIdx.y;
    const int i0 = blockIdx.x * 64;
    const int tid = threadIdx.x;
    const int wid = tid >> 5, lane = tid & 31;
    const float* sbase = probs + (size_t)b * SS * SS;

    for (int j = tid; j < SS; j += 512)
        c_s[j] = rsqrtf(g_colsum[b * SS + j]);
    if (tid < 64) rowdot_s[tid] = 0.0f;
    __syncthreads();

    const int wm = wid & 3, wn = wid >> 2;
    const int l4 = lane & 3, g8 = lane >> 2;

    float acc[2][4];
#pragma unroll
    for (int nb = 0; nb < 2; nb++)
#pragma unroll
        for (int i = 0; i < 4; i++) acc[nb][i] = 0.0f;

    const uint32_t Ab = smem_to_u32(As), Bb = smem_to_u32(Bs);
    const uint32_t aBase = Ab + (uint32_t)((wm * 16 + (lane & 15)) * K4_LDA + (lane >> 4) * 8) * 2;
    const int bkrow = (lane & 7) + 8 * ((lane >> 3) & 1);
    const uint32_t bBase = Bb + (uint32_t)(bkrow * K4_LDB + wn * 16 + 8 * (lane >> 4)) * 2;

    for (int j0 = 0; j0 < SS; j0 += 128) {
        {
            int jj = tid >> 2;
            int d4 = (tid & 3) * 16;
            const float cj = c_s[j0 + jj];
            const float* vsrc = g_qkv + (size_t)(b * SS + j0 + jj) * QKV_LD + 128 + d4;
            float4 v0 = *(const float4*)(vsrc);
            float4 v1 = *(const float4*)(vsrc + 4);
            float4 v2 = *(const float4*)(vsrc + 8);
            float4 v3 = *(const float4*)(vsrc + 12);
            float vv[16] = {v0.x,v0.y,v0.z,v0.w, v1.x,v1.y,v1.z,v1.w,
                            v2.x,v2.y,v2.z,v2.w, v3.x,v3.y,v3.z,v3.w};
            uint32_t hw[4], lw[4];
#pragma unroll
            for (int i = 0; i < 8; i++) {
                float w0 = vv[2*i] * cj, w1 = vv[2*i+1] * cj;
                float r0, r1;
                __nv_bfloat162 h = split_hi2(w0, w1, r0, r1);
                hw[i & 3] = *(uint32_t*)&h;
                __nv_bfloat162 lo2 = __halves2bfloat162(__float2bfloat16(r0), __float2bfloat16(r1));
                lw[i & 3] = *(uint32_t*)&lo2;
                if ((i & 3) == 3) {
                    *(uint4*)(Bs + jj * K4_LDB + d4 + (i >> 2) * 8)      = make_uint4(hw[0], hw[1], hw[2], hw[3]);
                    *(uint4*)(Bs + jj * K4_LDB + 64 + d4 + (i >> 2) * 8) = make_uint4(lw[0], lw[1], lw[2], lw[3]);
                }
            }
        }
#pragma unroll
        for (int it = 0; it < 4; it++) {
            int f = tid + 512 * it;
            int ii = f >> 5;
            int j4 = (f & 31) * 4;
            const float* p = sbase + (size_t)(i0 + ii) * SS + j0 + j4;
            float4 s4 = *(const float4*)p;
            float r0, r1, r2, r3;
            __nv_bfloat162 h01 = split_hi2(s4.x, s4.y, r0, r1);
            __nv_bfloat162 h23 = split_hi2(s4.z, s4.w, r2, r3);
            __nv_bfloat162 l01 = __halves2bfloat162(__float2bfloat16(r0), __float2bfloat16(r1));
            __nv_bfloat162 l23 = __halves2bfloat162(__float2bfloat16(r2), __float2bfloat16(r3));
            __nv_bfloat16* ar = As + ii * K4_LDA;
            *(uint2*)(ar + j4)       = make_uint2(*(uint32_t*)&h01, *(uint32_t*)&h23);
            *(uint2*)(ar + 128 + j4) = make_uint2(*(uint32_t*)&l01, *(uint32_t*)&l23);
            float rs = s4.x * c_s[j0 + j4 + 0] + s4.y * c_s[j0 + j4 + 1]
                     + s4.z * c_s[j0 + j4 + 2] + s4.w * c_s[j0 + j4 + 3];
#pragma unroll
            for (int o = 16; o; o >>= 1) rs += __shfl_xor_sync(0xFFFFFFFFu, rs, o);
            if (lane == 0) rowdot_s[ii] += rs;
        }
        __syncthreads();

#pragma unroll
        for (int ks = 0; ks < 8; ks++) {
            const int k0 = ks * 16;
            uint32_t ah[4], al[4];
            ldsm_x4(ah, aBase + (uint32_t)k0 * 2);
            ldsm_x4(al, aBase + (uint32_t)(128 + k0) * 2);
            uint32_t bh[4], bl[4];
            ldsm_x4_t(bh, bBase + (uint32_t)(k0 * K4_LDB) * 2);
            ldsm_x4_t(bl, bBase + (uint32_t)(k0 * K4_LDB + 64) * 2);
#pragma unroll
            for (int nb = 0; nb < 2; nb++) {
                const int pr = nb * 2;
                mma_bf16(acc[nb], ah, &bh[pr]);
                mma_bf16(acc[nb], al, &bh[pr]);
                mma_bf16(acc[nb], ah, &bl[pr]);
            }
        }
        __syncthreads();
    }

    if (tid < 64) g_rdi[b * SS + i0 + tid] = 1.0f / rowdot_s[tid];
    const float rdi0 = 1.0f / rowdot_s[wm * 16 + g8];
    const float rdi1 = 1.0f / rowdot_s[wm * 16 + g8 + 8];
#pragma unroll
    for (int nb = 0; nb < 2; nb++) {
        int row = i0 + wm * 16 + g8;
        int col = wn * 16 + nb * 8 + l4 * 2;
        *(float2*)(out + (size_t)(b * SS + row) * DD + col) =
            make_float2(acc[nb][0] * rdi0, acc[nb][1] * rdi0);
        *(float2*)(out + (size_t)(b * SS + row + 8) * DD + col) =
            make_float2(acc[nb][2] * rdi1, acc[nb][3] * rdi1);
    }
}

// ---------------------------------------------------------------- K4b: probs = s * c_j * rdi_i, pure streaming in-place
__global__ __launch_bounds__(256) void k4b_scale(float* __restrict__ probs)
{
    const int b = blockIdx.y;
    const int row = blockIdx.x;
    float* rp = probs + (size_t)b * SS * SS + (size_t)row * SS;
    const float rdi = g_rdi[b * SS + row];
    const float* cs = g_colsum + b * SS;
    int j4 = threadIdx.x * 4;
#pragma unroll
    for (int it = 0; it < 2; it++, j4 += 1024) {
        float4 s4 = *(float4*)(rp + j4);
        float c0 = rsqrtf(cs[j4 + 0]) * rdi;
        float c1 = rsqrtf(cs[j4 + 1]) * rdi;
        float c2 = rsqrtf(cs[j4 + 2]) * rdi;
        float c3 = rsqrtf(cs[j4 + 3]) * rdi;
        *(float4*)(rp + j4) = make_float4(s4.x * c0, s4.y * c1, s4.z * c2, s4.w * c3);
    }
}

// ----------------------------------------------------------------
extern "C" void kernel_launch(void* const* d_in, const int* in_sizes, int n_in,
                              void* d_out, int out_size)
{
    const float* x  = (const float*)d_in[0];
    const float* Wq = (const float*)d_in[1];
    const float* bq = (const float*)d_in[2];
    const float* Wk = (const float*)d_in[3];
    const float* bk = (const float*)d_in[4];
    const float* Wv = (const float*)d_in[5];
    const float* bv = (const float*)d_in[6];

    float* out   = (float*)d_out;                 // [B,S,64]
    float* probs = out + (size_t)BS * DD;         // [B,S,S]

    cudaFuncSetAttribute(k3_score, cudaFuncAttributeMaxDynamicSharedMemorySize, K3_SMEM);
    cudaFuncSetAttribute(k4a_gemm, cudaFuncAttributeMaxDynamicSharedMemorySize, K4_SMEM);

    k1_proj<<<BS / 64, 256>>>(x, Wq, bq, Wk, bk, Wv, bv);
    k2_norm<<<(BS * 3 * 32) / 256, 256>>>();
    k3_score<<<dim3(16, 16, BB), 512, K3_SMEM>>>(probs);
    k4a_gemm<<<dim3(SS / 64, BB), 512, K4_SMEM>>>(out, probs);
    k4b_scale<<<dim3(SS, BB), 256>>>(probs);
}

// round 16
// speedup vs baseline: 1.2942x; 1.2942x over previous
#include <cuda_runtime.h>
#include <cuda_bf16.h>
#include <cstdint>
#include <math.h>

#define BB 8
#define SS 2048
#define HH 1024
#define DD 64
#define BS (BB*SS)      /* 16384 */
#define QKV_LD 192

#define CLIP_HI 0.9999998807907104f
#define PEXP (-65.5f)

// ---------------------------------------------------------------- scratch
__device__ float g_qkv[BS * QKV_LD];               // [row][ q(64) | k(64) | v(64) ]
__device__ float g_colsum[BS];                     // [B][S]
__device__ float g_rdi[BS];                        // [B][S] 1/rowdot
__device__ __nv_bfloat16 g_qsp[(size_t)BS * 128];  // [row][ q_hi(64) | q_lo(64) ]
__device__ __nv_bfloat16 g_ksp[(size_t)BS * 128];  // [row][ k_hi(64) | k_lo(64) ]

// ---------------------------------------------------------------- warp MMA helpers (arch-stable PTX)
__device__ __forceinline__ uint32_t smem_to_u32(const void* smem_ptr) {
    uint32_t addr;
    asm("{ .reg .u64 tmp; cvta.to.shared.u64 tmp, %1; cvt.u32.u64 %0, tmp; }"
        : "=r"(addr) : "l"(smem_ptr));
    return addr;
}

__device__ __forceinline__ void ldsm_x4(uint32_t* r, uint32_t addr) {
    asm volatile("ldmatrix.sync.aligned.m8n8.x4.shared.b16 {%0,%1,%2,%3}, [%4];"
        : "=r"(r[0]), "=r"(r[1]), "=r"(r[2]), "=r"(r[3]) : "r"(addr));
}
__device__ __forceinline__ void ldsm_x4_t(uint32_t* r, uint32_t addr) {
    asm volatile("ldmatrix.sync.aligned.m8n8.x4.trans.shared.b16 {%0,%1,%2,%3}, [%4];"
        : "=r"(r[0]), "=r"(r[1]), "=r"(r[2]), "=r"(r[3]) : "r"(addr));
}
__device__ __forceinline__ void mma_bf16(float* d, const uint32_t* a, const uint32_t* b) {
    asm volatile(
        "mma.sync.aligned.m16n8k16.row.col.f32.bf16.bf16.f32 "
        "{%0,%1,%2,%3}, {%4,%5,%6,%7}, {%8,%9}, {%0,%1,%2,%3};"
        : "+f"(d[0]), "+f"(d[1]), "+f"(d[2]), "+f"(d[3])
        : "r"(a[0]), "r"(a[1]), "r"(a[2]), "r"(a[3]), "r"(b[0]), "r"(b[1]));
}

__device__ __forceinline__ float score_fn(float cosv) {
    cosv = fminf(fmaxf(cosv, -CLIP_HI), CLIP_HI);
    float gd = acosf(cosv);
    float l;
    asm("lg2.approx.f32 %0, %1;" : "=f"(l) : "f"(1.0f + gd));
    float e;
    asm("ex2.approx.f32 %0, %1;" : "=f"(e) : "f"(PEXP * l));
    return e;
}

__device__ __forceinline__ __nv_bfloat162 split_hi2(float a, float b,
                                                    float& ra, float& rb) {
    __nv_bfloat16 h0 = __float2bfloat16(a);
    __nv_bfloat16 h1 = __float2bfloat16(b);
    ra = a - __bfloat162float(h0);
    rb = b - __bfloat162float(h1);
    return __halves2bfloat162(h0, h1);
}

// ---------------------------------------------------------------- K1: fused q|k|v projections via bf16 3-split mma (proven R13)
#define K1_AK 72
#define K1_BK 392

__global__ __launch_bounds__(256, 2) void k1_proj(
    const float* __restrict__ x,
    const float* __restrict__ Wq, const float* __restrict__ bq,
    const float* __restrict__ Wk, const float* __restrict__ bk,
    const float* __restrict__ Wv, const float* __restrict__ bv)
{
    __shared__ __nv_bfloat16 As[64][K1_AK];
    __shared__ __nv_bfloat16 Bs[32][K1_BK];
    __shared__ float s_bias[192];

    const int m0 = blockIdx.x * 64;
    const int tid = threadIdx.x;
    const int wid = tid >> 5, lane = tid & 31;
    const int wm = wid & 3, wn = wid >> 2;

    if (tid < 192) {
        const float* bsrc = (tid < 64) ? bq : ((tid < 128) ? bk : bv);
        s_bias[tid] = bsrc[tid & 63];
    }

    float acc[12][4];
#pragma unroll
    for (int nb = 0; nb < 12; nb++)
#pragma unroll
        for (int i = 0; i < 4; i++) acc[nb][i] = 0.0f;

    const uint32_t Ab = smem_to_u32(As), Bb = smem_to_u32(Bs);
    const uint32_t aBase = Ab + (uint32_t)((wm * 16 + (lane & 15)) * K1_AK + (lane >> 4) * 8) * 2;
    const int bkrow = (lane & 7) + 8 * ((lane >> 3) & 1);
    const uint32_t bBase = Bb + (uint32_t)(bkrow * K1_BK + wn * 96 + 8 * (lane >> 4)) * 2;

    for (int k0 = 0; k0 < HH; k0 += 32) {
#pragma unroll
        for (int it = 0; it < 2; it++) {
            int f = tid + 256 * it;
            int row = f >> 3;
            int k4 = (f & 7) * 4;
            float4 v = *(const float4*)(x + (size_t)(m0 + row) * HH + k0 + k4);
            float r0, r1, r2, r3;
            __nv_bfloat162 h01 = split_hi2(v.x, v.y, r0, r1);
            __nv_bfloat162 h23 = split_hi2(v.z, v.w, r2, r3);
            *(__nv_bfloat162*)&As[row][k4]          = h01;
            *(__nv_bfloat162*)&As[row][k4 + 2]      = h23;
            *(__nv_bfloat162*)&As[row][32 + k4]     = __halves2bfloat162(__float2bfloat16(r0), __float2bfloat16(r1));
            *(__nv_bfloat162*)&As[row][32 + k4 + 2] = __halves2bfloat162(__float2bfloat16(r2), __float2bfloat16(r3));
        }
#pragma unroll
        for (int it = 0; it < 6; it++) {
            int f = tid + 256 * it;
            int which = f >> 9;
            int kr = (f >> 4) & 31;
            int n4 = (f & 15) * 4;
            const float* W = (which == 0) ? Wq : ((which == 1) ? Wk : Wv);
            float4 v = *(const float4*)(W + (size_t)(k0 + kr) * DD + n4);
            int n = which * 64 + n4;
            float r0, r1, r2, r3;
            __nv_bfloat162 h01 = split_hi2(v.x, v.y, r0, r1);
            __nv_bfloat162 h23 = split_hi2(v.z, v.w, r2, r3);
            *(__nv_bfloat162*)&Bs[kr][n]           = h01;
            *(__nv_bfloat162*)&Bs[kr][n + 2]       = h23;
            *(__nv_bfloat162*)&Bs[kr][192 + n]     = __halves2bfloat162(__float2bfloat16(r0), __float2bfloat16(r1));
            *(__nv_bfloat162*)&Bs[kr][192 + n + 2] = __halves2bfloat162(__float2bfloat16(r2), __float2bfloat16(r3));
        }
        __syncthreads();

#pragma unroll
        for (int ks = 0; ks < 2; ks++) {
            const int kk = ks * 16;
            uint32_t ah[4], al[4];
            ldsm_x4(ah, aBase + (uint32_t)kk * 2);
            ldsm_x4(al, aBase + (uint32_t)(32 + kk) * 2);
#pragma unroll
            for (int nt = 0; nt < 6; nt++) {
                uint32_t bh[4], bl[4];
                ldsm_x4_t(bh, bBase + (uint32_t)(kk * K1_BK + nt * 16) * 2);
                ldsm_x4_t(bl, bBase + (uint32_t)(kk * K1_BK + 192 + nt * 16) * 2);
#pragma unroll
                for (int p = 0; p < 2; p++) {
                    const int nb = nt * 2 + p;
                    mma_bf16(acc[nb], ah, &bh[p * 2]);
                    mma_bf16(acc[nb], al, &bh[p * 2]);
                    mma_bf16(acc[nb], ah, &bl[p * 2]);
                }
            }
        }
        __syncthreads();
    }

    const int g8 = lane >> 2, l4 = lane & 3;
#pragma unroll
    for (int nb = 0; nb < 12; nb++) {
        int col = wn * 96 + nb * 8 + l4 * 2;
        float2 bb = *(float2*)&s_bias[col];
        int row = m0 + wm * 16 + g8;
        *(float2*)(g_qkv + (size_t)row * QKV_LD + col) =
            make_float2(acc[nb][0] + bb.x, acc[nb][1] + bb.y);
        *(float2*)(g_qkv + (size_t)(row + 8) * QKV_LD + col) =
            make_float2(acc[nb][2] + bb.x, acc[nb][3] + bb.y);
    }
}

// ---------------------------------------------------------------- K2: L2 normalize + bf16 hi/lo split + colsum zero (k0 fused)
__global__ void k2_norm() {
    int gt = blockIdx.x * blockDim.x + threadIdx.x;
    if (gt < BS) g_colsum[gt] = 0.0f;
    int gw = gt >> 5;
    int lane = threadIdx.x & 31;
    if (gw >= BS * 3) return;
    int row = gw / 3;
    int mat = gw - row * 3;
    float* p = g_qkv + (size_t)row * QKV_LD + mat * 64;
    float2 v = *(float2*)(p + lane * 2);
    float ss = v.x * v.x + v.y * v.y;
#pragma unroll
    for (int o = 16; o; o >>= 1) ss += __shfl_xor_sync(0xFFFFFFFFu, ss, o);
    float inv = 1.0f / fmaxf(sqrtf(ss), 1e-12f);
    float a0 = v.x * inv, a1 = v.y * inv;
    if (mat == 2) {
        *(float2*)(p + lane * 2) = make_float2(a0, a1);
    } else {
        __nv_bfloat16* dst = (mat == 0 ? g_qsp : g_ksp) + (size_t)row * 128;
        __nv_bfloat16 h0 = __float2bfloat16(a0);
        __nv_bfloat16 h1 = __float2bfloat16(a1);
        __nv_bfloat16 l0 = __float2bfloat16(a0 - __bfloat162float(h0));
        __nv_bfloat16 l1 = __float2bfloat16(a1 - __bfloat162float(h1));
        *(__nv_bfloat162*)(dst + lane * 2)      = __halves2bfloat162(h0, h1);
        *(__nv_bfloat162*)(dst + 64 + lane * 2) = __halves2bfloat162(l0, l1);
    }
}

// ---------------------------------------------------------------- K3: QK^T via mma.sync bf16 3-split, 128x128, 256 thr (proven shape)
#define LDA 136
#define K3_SMEM (2 * 128 * LDA * 2)   /* 69632 bytes */

__global__ __launch_bounds__(256, 2) void k3_score(float* __restrict__ probs)
{
    extern __shared__ __nv_bfloat16 sm[];
    __nv_bfloat16* As = sm;
    __nv_bfloat16* Bs = sm + 128 * LDA;
    __shared__ float s_colsum[128];

    const int b  = blockIdx.z;
    const int m0 = blockIdx.y * 128;
    const int n0 = blockIdx.x * 128;
    const int tid = threadIdx.x;
    const int wid = tid >> 5, lane = tid & 31;

    if (tid < 128) s_colsum[tid] = 0.0f;

    const uint4* qg = (const uint4*)(g_qsp + (size_t)(b * SS + m0) * 128);
    const uint4* kg = (const uint4*)(g_ksp + (size_t)(b * SS + n0) * 128);
#pragma unroll
    for (int it = 0; it < 8; it++) {
        int f = tid + 256 * it;
        int row = f >> 4;
        int i = f & 15;
        *(uint4*)((char*)As + row * (LDA * 2) + i * 16) = qg[row * 16 + i];
        *(uint4*)((char*)Bs + row * (LDA * 2) + i * 16) = kg[row * 16 + i];
    }
    __syncthreads();

    const uint32_t Ab = smem_to_u32(As), Bb = smem_to_u32(Bs);
    const int arow = lane & 15, ak8 = (lane >> 4) * 8;
    const uint32_t aBase = Ab + (uint32_t)(((wid & 3) * 32 + arow) * LDA + ak8) * 2;
    const int bn  = (lane & 7) + ((lane >> 4) << 3);
    const int bk8 = ((lane >> 3) & 1) * 8;
    const uint32_t bBase = Bb + (uint32_t)(((wid >> 2) * 64 + bn) * LDA + bk8) * 2;

    float acc[2][8][4];
#pragma unroll
    for (int mt = 0; mt < 2; mt++)
#pragma unroll
        for (int nb = 0; nb < 8; nb++)
#pragma unroll
            for (int i = 0; i < 4; i++) acc[mt][nb][i] = 0.0f;

    // 3 product segments: (hi,hi), (lo,hi), (hi,lo) — lo.lo dropped (~2^-18 rel)
    const int ai[3] = {0, 1, 0};
    const int bi[3] = {0, 0, 1};
#pragma unroll
    for (int seg = 0; seg < 3; seg++) {
        const int aoff = ai[seg] * 64, boff = bi[seg] * 64;
#pragma unroll
        for (int ks = 0; ks < 4; ks++) {
            const int k0 = ks * 16;
            uint32_t af[2][4];
            ldsm_x4(af[0], aBase + (uint32_t)(aoff + k0) * 2);
            ldsm_x4(af[1], aBase + (uint32_t)(16 * LDA + aoff + k0) * 2);
            uint32_t bf[4][4];
#pragma unroll
            for (int nt = 0; nt < 4; nt++)
                ldsm_x4(bf[nt], bBase + (uint32_t)(nt * 16 * LDA + boff + k0) * 2);
#pragma unroll
            for (int mt = 0; mt < 2; mt++)
#pragma unroll
                for (int nb = 0; nb < 8; nb++)
                    mma_bf16(acc[mt][nb], af[mt], &bf[nb >> 1][(nb & 1) * 2]);
        }
    }

    const int g = lane >> 2, cq = (lane & 3) * 2;
    const int colbase = n0 + (wid >> 2) * 64 + cq;
    float* pb = probs + (size_t)b * SS * SS;

    float colacc[16];
#pragma unroll
    for (int i = 0; i < 16; i++) colacc[i] = 0.0f;

#pragma unroll
    for (int mt = 0; mt < 2; mt++) {
#pragma unroll
        for (int h = 0; h < 2; h++) {
            const int row = m0 + (wid & 3) * 32 + mt * 16 + h * 8 + g;
            float* rp = pb + (size_t)row * SS + colbase;
#pragma unroll
            for (int nb = 0; nb < 8; nb++) {
                float x0 = score_fn(acc[mt][nb][h * 2 + 0]);
                float x1 = score_fn(acc[mt][nb][h * 2 + 1]);
                colacc[nb * 2 + 0] += x0;
                colacc[nb * 2 + 1] += x1;
                *(float2*)(rp + nb * 8) = make_float2(x0, x1);
            }
        }
    }

#pragma unroll
    for (int nb = 0; nb < 8; nb++) {
        float s0 = colacc[nb * 2], s1 = colacc[nb * 2 + 1];
#pragma unroll
        for (int o = 4; o <= 16; o <<= 1) {
            s0 += __shfl_xor_sync(0xFFFFFFFFu, s0, o);
            s1 += __shfl_xor_sync(0xFFFFFFFFu, s1, o);
        }
        if (lane < 4) {
            atomicAdd(&s_colsum[(wid >> 2) * 64 + nb * 8 + lane * 2 + 0], s0);
            atomicAdd(&s_colsum[(wid >> 2) * 64 + nb * 8 + lane * 2 + 1], s1);
        }
    }

    __syncthreads();
    if (tid < 128) atomicAdd(&g_colsum[b * SS + n0 + tid], s_colsum[tid]);
}

// ---------------------------------------------------------------- K4a: out = (S_raw @ (c*v)) * rdi (proven R14)
#define K4_LDA 264
#define K4_LDB 136
#define K4_SMEM ((64 * K4_LDA + 128 * K4_LDB) * 2)   /* 68608 bytes */

__global__ __launch_bounds__(512, 2) void k4a_gemm(float* __restrict__ out, const float* __restrict__ probs)
{
    extern __shared__ __nv_bfloat16 k4sm[];
    __nv_bfloat16* As = k4sm;                   // [64][K4_LDA]  raw s hi|lo
    __nv_bfloat16* Bs = k4sm + 64 * K4_LDA;     // [128][K4_LDB] w=c*v hi|lo
    __shared__ float c_s[SS];
    __shared__ float rowdot_s[64];

    const int b  = blockIdx.y;
    const int i0 = blockIdx.x * 64;
    const int tid = threadIdx.x;
    const int wid = tid >> 5, lane = tid & 31;
    const float* sbase = probs + (size_t)b * SS * SS;

    for (int j = tid; j < SS; j += 512)
        c_s[j] = rsqrtf(g_colsum[b * SS + j]);
    if (tid < 64) rowdot_s[tid] = 0.0f;
    __syncthreads();

    const int wm = wid & 3, wn = wid >> 2;
    const int l4 = lane & 3, g8 = lane >> 2;

    float acc[2][4];
#pragma unroll
    for (int nb = 0; nb < 2; nb++)
#pragma unroll
        for (int i = 0; i < 4; i++) acc[nb][i] = 0.0f;

    const uint32_t Ab = smem_to_u32(As), Bb = smem_to_u32(Bs);
    const uint32_t aBase = Ab + (uint32_t)((wm * 16 + (lane & 15)) * K4_LDA + (lane >> 4) * 8) * 2;
    const int bkrow = (lane & 7) + 8 * ((lane >> 3) & 1);
    const uint32_t bBase = Bb + (uint32_t)(bkrow * K4_LDB + wn * 16 + 8 * (lane >> 4)) * 2;

    for (int j0 = 0; j0 < SS; j0 += 128) {
        {
            int jj = tid >> 2;
            int d4 = (tid & 3) * 16;
            const float cj = c_s[j0 + jj];
            const float* vsrc = g_qkv + (size_t)(b * SS + j0 + jj) * QKV_LD + 128 + d4;
            float4 v0 = *(const float4*)(vsrc);
            float4 v1 = *(const float4*)(vsrc + 4);
            float4 v2 = *(const float4*)(vsrc + 8);
            float4 v3 = *(const float4*)(vsrc + 12);
            float vv[16] = {v0.x,v0.y,v0.z,v0.w, v1.x,v1.y,v1.z,v1.w,
                            v2.x,v2.y,v2.z,v2.w, v3.x,v3.y,v3.z,v3.w};
            uint32_t hw[4], lw[4];
#pragma unroll
            for (int i = 0; i < 8; i++) {
                float w0 = vv[2*i] * cj, w1 = vv[2*i+1] * cj;
                float r0, r1;
                __nv_bfloat162 h = split_hi2(w0, w1, r0, r1);
                hw[i & 3] = *(uint32_t*)&h;
                __nv_bfloat162 lo2 = __halves2bfloat162(__float2bfloat16(r0), __float2bfloat16(r1));
                lw[i & 3] = *(uint32_t*)&lo2;
                if ((i & 3) == 3) {
                    *(uint4*)(Bs + jj * K4_LDB + d4 + (i >> 2) * 8)      = make_uint4(hw[0], hw[1], hw[2], hw[3]);
                    *(uint4*)(Bs + jj * K4_LDB + 64 + d4 + (i >> 2) * 8) = make_uint4(lw[0], lw[1], lw[2], lw[3]);
                }
            }
        }
#pragma unroll
        for (int it = 0; it < 4; it++) {
            int f = tid + 512 * it;
            int ii = f >> 5;
            int j4 = (f & 31) * 4;
            const float* p = sbase + (size_t)(i0 + ii) * SS + j0 + j4;
            float4 s4 = *(const float4*)p;
            float r0, r1, r2, r3;
            __nv_bfloat162 h01 = split_hi2(s4.x, s4.y, r0, r1);
            __nv_bfloat162 h23 = split_hi2(s4.z, s4.w, r2, r3);
            __nv_bfloat162 l01 = __halves2bfloat162(__float2bfloat16(r0), __float2bfloat16(r1));
            __nv_bfloat162 l23 = __halves2bfloat162(__float2bfloat16(r2), __float2bfloat16(r3));
            __nv_bfloat16* ar = As + ii * K4_LDA;
            *(uint2*)(ar + j4)       = make_uint2(*(uint32_t*)&h01, *(uint32_t*)&h23);
            *(uint2*)(ar + 128 + j4) = make_uint2(*(uint32_t*)&l01, *(uint32_t*)&l23);
            float rs = s4.x * c_s[j0 + j4 + 0] + s4.y * c_s[j0 + j4 + 1]
                     + s4.z * c_s[j0 + j4 + 2] + s4.w * c_s[j0 + j4 + 3];
#pragma unroll
            for (int o = 16; o; o >>= 1) rs += __shfl_xor_sync(0xFFFFFFFFu, rs, o);
            if (lane == 0) rowdot_s[ii] += rs;
        }
        __syncthreads();

#pragma unroll
        for (int ks = 0; ks < 8; ks++) {
            const int k0 = ks * 16;
            uint32_t ah[4], al[4];
            ldsm_x4(ah, aBase + (uint32_t)k0 * 2);
            ldsm_x4(al, aBase + (uint32_t)(128 + k0) * 2);
            uint32_t bh[4], bl[4];
            ldsm_x4_t(bh, bBase + (uint32_t)(k0 * K4_LDB) * 2);
            ldsm_x4_t(bl, bBase + (uint32_t)(k0 * K4_LDB + 64) * 2);
#pragma unroll
            for (int nb = 0; nb < 2; nb++) {
                const int pr = nb * 2;
                mma_bf16(acc[nb], ah, &bh[pr]);
                mma_bf16(acc[nb], al, &bh[pr]);
                mma_bf16(acc[nb], ah, &bl[pr]);
            }
        }
        __syncthreads();
    }

    if (tid < 64) g_rdi[b * SS + i0 + tid] = 1.0f / rowdot_s[tid];
    const float rdi0 = 1.0f / rowdot_s[wm * 16 + g8];
    const float rdi1 = 1.0f / rowdot_s[wm * 16 + g8 + 8];
#pragma unroll
    for (int nb = 0; nb < 2; nb++) {
        int row = i0 + wm * 16 + g8;
        int col = wn * 16 + nb * 8 + l4 * 2;
        *(float2*)(out + (size_t)(b * SS + row) * DD + col) =
            make_float2(acc[nb][0] * rdi0, acc[nb][1] * rdi0);
        *(float2*)(out + (size_t)(b * SS + row + 8) * DD + col) =
            make_float2(acc[nb][2] * rdi1, acc[nb][3] * rdi1);
    }
}

// ---------------------------------------------------------------- K4b: probs = s * c_j * rdi_i, pure streaming in-place
__global__ __launch_bounds__(256) void k4b_scale(float* __restrict__ probs)
{
    const int b = blockIdx.y;
    const int row = blockIdx.x;
    float* rp = probs + (size_t)b * SS * SS + (size_t)row * SS;
    const float rdi = g_rdi[b * SS + row];
    const float* cs = g_colsum + b * SS;
    int j4 = threadIdx.x * 4;
#pragma unroll
    for (int it = 0; it < 2; it++, j4 += 1024) {
        float4 s4 = *(float4*)(rp + j4);
        float c0 = rsqrtf(cs[j4 + 0]) * rdi;
        float c1 = rsqrtf(cs[j4 + 1]) * rdi;
        float c2 = rsqrtf(cs[j4 + 2]) * rdi;
        float c3 = rsqrtf(cs[j4 + 3]) * rdi;
        *(float4*)(rp + j4) = make_float4(s4.x * c0, s4.y * c1, s4.z * c2, s4.w * c3);
    }
}

// ----------------------------------------------------------------
extern "C" void kernel_launch(void* const* d_in, const int* in_sizes, int n_in,
                              void* d_out, int out_size)
{
    const float* x  = (const float*)d_in[0];
    const float* Wq = (const float*)d_in[1];
    const float* bq = (const float*)d_in[2];
    const float* Wk = (const float*)d_in[3];
    const float* bk = (const float*)d_in[4];
    const float* Wv = (const float*)d_in[5];
    const float* bv = (const float*)d_in[6];

    float* out   = (float*)d_out;                 // [B,S,64]
    float* probs = out + (size_t)BS * DD;         // [B,S,S]

    cudaFuncSetAttribute(k3_score, cudaFuncAttributeMaxDynamicSharedMemorySize, K3_SMEM);
    cudaFuncSetAttribute(k4a_gemm, cudaFuncAttributeMaxDynamicSharedMemorySize, K4_SMEM);

    k1_proj<<<BS / 64, 256>>>(x, Wq, bq, Wk, bk, Wv, bv);
    k2_norm<<<(BS * 3 * 32) / 256, 256>>>();
    k3_score<<<dim3(16, 16, BB), 256, K3_SMEM>>>(probs);
    k4a_gemm<<<dim3(SS / 64, BB), 512, K4_SMEM>>>(out, probs);
    k4b_scale<<<dim3(SS, BB), 256>>>(probs);
}